// round 9
// baseline (speedup 1.0000x reference)
#include <cuda_runtime.h>
#include <math.h>

#define MAX_DIM 2048
#define GTHREADS 256

// ---------------- Fast path: nq=11, real-only output.
// U = (⊗H) D (⊗H), D(n)=e^{i φ(n)}; for real input and real-part output:
//   out = WHT( WHT(s) ⊙ cosφ ) / 2048   (all real arithmetic)
// Network: bits0..2 in regs, bits3..7 via shuffle, bits8..10 via one smem
// permute. 512 thr/CTA = 2 vectors -> 128 CTAs (one wave on 148 SMs).
#define FDIM   2048
#define FNQ    11
#define FTHREADS 512
#define SPAD(n) ((n) + ((n) >> 5))

__global__ __launch_bounds__(FTHREADS)
void rx_wht_kernel(const float* __restrict__ state,
                   const float* __restrict__ weights,
                   float* __restrict__ out,
                   int nvec, int nblocks)
{
    __shared__ float s_a[SPAD(2 * FDIM - 1) + 1];
    __shared__ float hh[2][FNQ];       // half-angle per amplitude bit
    __shared__ float cJ[2][8], sJ[2][8];

    const int t   = threadIdx.x;
    const int vid = t >> 8;
    const int tl  = t & 255;
    const int w   = tl >> 5;           // amp bits 8..10 pre-permute
    const int l   = tl & 31;           // amp bits 3..7
    const int vec = blockIdx.x * 2 + vid;
    const bool active = (vec < nvec);
    const int bl = active ? (vec % nblocks) : 0;

    float x[8];

    if (active) {
        const float4* s4 = (const float4*)(state + (size_t)vec * FDIM) + tl * 2;
        const float4 v0 = s4[0];
        const float4 v1 = s4[1];
        x[0] = v0.x; x[1] = v0.y; x[2] = v0.z; x[3] = v0.w;
        x[4] = v1.x; x[5] = v1.y; x[6] = v1.z; x[7] = v1.w;
    } else {
        #pragma unroll
        for (int j = 0; j < 8; j++) x[j] = 0.0f;
    }

    // Amplitude bit b hosts qubit (10-b): hh[b] = weights[10-b]/2.
    if (tl < FNQ && active)
        hh[vid][tl] = 0.5f * weights[bl * FNQ + (10 - tl)];
    // Phase table over register bits (amp bits 8..10 -> qubits 2,1,0),
    // with the final 1/2048 WHT normalization folded in.
    if (tl < 8 && active) {
        float pj = 0.0f;
        #pragma unroll
        for (int tt = 0; tt < 3; tt++) {
            const float h = 0.5f * weights[bl * FNQ + (2 - tt)];
            pj += ((tl >> tt) & 1) ? h : -h;
        }
        float s, c;
        sincosf(pj, &s, &c);
        cJ[vid][tl] = c * (1.0f / 2048.0f);
        sJ[vid][tl] = s * (1.0f / 2048.0f);
    }
    __syncthreads();

    // ---- forward WHT: reg bits 0..2
    #pragma unroll
    for (int b = 0; b < 3; b++) {
        const int m = 1 << b;
        #pragma unroll
        for (int j = 0; j < 8; j++)
            if ((j & m) == 0) {
                const int h = j | m;
                const float lo = x[j], hi = x[h];
                x[j] = lo + hi;
                x[h] = lo - hi;
            }
    }
    // ---- forward WHT: lane bits 3..7 (shuffle; new = partner + sgn*own)
    #pragma unroll
    for (int k = 0; k < 5; k++) {
        const float sgn = ((l >> k) & 1) ? -1.0f : 1.0f;
        #pragma unroll
        for (int j = 0; j < 8; j++) {
            const float p = __shfl_xor_sync(0xffffffffu, x[j], 1 << k);
            x[j] = fmaf(sgn, x[j], p);
        }
    }
    // ---- permute: swap warp bits <-> reg bits
    #pragma unroll
    for (int j = 0; j < 8; j++)
        s_a[SPAD((vid << 11) | (tl << 3) | j)] = x[j];
    __syncthreads();
    #pragma unroll
    for (int j = 0; j < 8; j++)
        x[j] = s_a[SPAD((vid << 11) | (j << 8) | (l << 3) | w)];
    // ---- forward WHT: amp bits 8..10 (now reg bits)
    #pragma unroll
    for (int b = 0; b < 3; b++) {
        const int m = 1 << b;
        #pragma unroll
        for (int j = 0; j < 8; j++)
            if ((j & m) == 0) {
                const int h = j | m;
                const float lo = x[j], hi = x[h];
                x[j] = lo + hi;
                x[h] = lo - hi;
            }
    }

    // ---- diagonal: multiply by cos(phi)/2048
    // fixed bits: amp bits 0..2 = w, amp bits 3..7 = l
    float phi = 0.0f;
    #pragma unroll
    for (int b = 0; b < 3; b++)
        phi += ((w >> b) & 1) ? hh[vid][b] : -hh[vid][b];
    #pragma unroll
    for (int b = 3; b < 8; b++)
        phi += ((l >> (b - 3)) & 1) ? hh[vid][b] : -hh[vid][b];
    float sF, cF;
    sincosf(phi, &sF, &cF);
    #pragma unroll
    for (int j = 0; j < 8; j++)
        x[j] *= fmaf(cF, cJ[vid][j], -sF * sJ[vid][j]);

    // ---- inverse WHT: amp bits 8..10
    #pragma unroll
    for (int b = 0; b < 3; b++) {
        const int m = 1 << b;
        #pragma unroll
        for (int j = 0; j < 8; j++)
            if ((j & m) == 0) {
                const int h = j | m;
                const float lo = x[j], hi = x[h];
                x[j] = lo + hi;
                x[h] = lo - hi;
            }
    }
    // ---- permute back (each thread rewrites exactly the slots it read)
    #pragma unroll
    for (int j = 0; j < 8; j++)
        s_a[SPAD((vid << 11) | (j << 8) | (l << 3) | w)] = x[j];
    __syncthreads();
    #pragma unroll
    for (int j = 0; j < 8; j++)
        x[j] = s_a[SPAD((vid << 11) | (tl << 3) | j)];
    // ---- inverse WHT: lane bits 3..7
    #pragma unroll
    for (int k = 0; k < 5; k++) {
        const float sgn = ((l >> k) & 1) ? -1.0f : 1.0f;
        #pragma unroll
        for (int j = 0; j < 8; j++) {
            const float p = __shfl_xor_sync(0xffffffffu, x[j], 1 << k);
            x[j] = fmaf(sgn, x[j], p);
        }
    }
    // ---- inverse WHT: reg bits 0..2
    #pragma unroll
    for (int b = 0; b < 3; b++) {
        const int m = 1 << b;
        #pragma unroll
        for (int j = 0; j < 8; j++)
            if ((j & m) == 0) {
                const int h = j | m;
                const float lo = x[j], hi = x[h];
                x[j] = lo + hi;
                x[h] = lo - hi;
            }
    }

    // ---- coalesced real-only store
    if (active) {
        float4* o4 = (float4*)out + (size_t)vec * (FDIM / 4) + tl * 2;
        o4[0] = make_float4(x[0], x[1], x[2], x[3]);
        o4[1] = make_float4(x[4], x[5], x[6], x[7]);
    }
}

// ---------------- Generic fallback (proven R7 kernel, fully guarded).
__global__ __launch_bounds__(GTHREADS)
void rx_layer_kernel(const float* __restrict__ state,
                     const float* __restrict__ weights,
                     float* __restrict__ out,
                     int nvec, int nblocks, int nq, int dim,
                     long stateLimF, long wLimF, long outCapF,
                     int interleaved)
{
    __shared__ __align__(16) float2 amp[MAX_DIM];
    __shared__ float sa[32];
    __shared__ float sb[32];

    const int tid = threadIdx.x;

    for (int vec = blockIdx.x; vec < nvec; vec += gridDim.x) {
        const int bl = vec % nblocks;
        const long sbase = (long)vec * dim;
        for (int i = tid; i < dim; i += GTHREADS) {
            const long gi = sbase + i;
            amp[i] = make_float2((gi < stateLimF) ? state[gi] : 0.0f, 0.0f);
        }
        if (tid < nq) {
            const long widx = (long)bl * nq + tid;
            const float wv = (widx < wLimF) ? weights[widx] : 0.0f;
            float s, c;
            sincosf(wv * 0.5f, &s, &c);
            sa[tid] = c;
            sb[tid] = s;
        }
        __syncthreads();
        for (int q = 0; q < nq; q++) {
            const int   st   = 1 << (nq - 1 - q);
            const float a    = sa[q];
            const float b    = sb[q];
            const int   half = dim >> 1;
            for (int p = tid; p < half; p += GTHREADS) {
                const int lo = ((p & ~(st - 1)) << 1) | (p & (st - 1));
                const int hi = lo + st;
                const float2 xx = amp[lo];
                const float2 yy = amp[hi];
                amp[lo] = make_float2(fmaf(a, xx.x,  b * yy.y),
                                      fmaf(a, xx.y, -b * yy.x));
                amp[hi] = make_float2(fmaf(a, yy.x,  b * xx.y),
                                      fmaf(a, yy.y, -b * xx.x));
            }
            __syncthreads();
        }
        if (interleaved) {
            const long obase = 2L * (long)vec * dim;
            for (int i = tid; i < dim; i += GTHREADS) {
                const long fo = obase + 2L * i;
                if (fo + 1 < outCapF) {
                    out[fo]     = amp[i].x;
                    out[fo + 1] = amp[i].y;
                }
            }
        } else {
            const long obase = (long)vec * dim;
            for (int i = tid; i < dim; i += GTHREADS) {
                const long fo = obase + i;
                if (fo < outCapF) out[fo] = amp[i].x;
            }
        }
        __syncthreads();
    }
}

extern "C" void kernel_launch(void* const* d_in, const int* in_sizes, int n_in,
                              void* d_out, int out_size)
{
    int si = 0;
    for (int i = 1; i < n_in; i++) if (in_sizes[i] > in_sizes[si]) si = i;
    int wi = (si == 0) ? ((n_in > 1) ? 1 : 0) : 0;

    const float* state   = (const float*)d_in[si];
    const float* weights = (const float*)d_in[wi];
    const long stateE = in_sizes[si];
    const long wE     = in_sizes[wi];

    int nq = -1, dim = 0, nvec = 0, nblocks = 1;
    for (int q = 1; q <= 20; q++) {
        if (wE <= 0 || wE % q) continue;
        const long d = 1L << q;
        if (d > MAX_DIM || stateE % d) continue;
        const long nv = stateE / d;
        const long nb = wE / q;
        if (nb <= 0 || nv % nb) continue;
        nq = q; dim = (int)d; nvec = (int)nv; nblocks = (int)nb;
    }
    if (nq < 0) { nq = 1; dim = 2; nvec = (int)(stateE >= 2 ? stateE / 2 : 1); nblocks = 1; }

    const long outCapF = out_size;   // floats: minimal safe interpretation
    const int interleaved = (outCapF >= 2L * (long)nvec * dim) ? 1 : 0;

    const bool fast = (nq == FNQ) && (dim == FDIM) && nvec >= 1 &&
                      (stateE == (long)nvec * FDIM) &&
                      (wE == (long)nblocks * FNQ) &&
                      !interleaved &&
                      (outCapF >= (long)nvec * FDIM);

    if (fast) {
        const int grid = (nvec + 1) / 2;
        rx_wht_kernel<<<grid, FTHREADS>>>(state, weights, (float*)d_out,
                                          nvec, nblocks);
    } else {
        int grid = nvec < 2048 ? nvec : 2048;
        if (grid < 1) grid = 1;
        rx_layer_kernel<<<grid, GTHREADS>>>(state, weights, (float*)d_out,
                                            nvec, nblocks, nq, dim,
                                            stateE, wE, outCapF, interleaved);
    }
}

// round 10
// speedup vs baseline: 1.3478x; 1.3478x over previous
#include <cuda_runtime.h>
#include <math.h>

#define MAX_DIM 2048
#define GTHREADS 256

// ---------------- Fast path: nq=11, real-only output.
// U = (⊗H) D (⊗H), D(n)=e^{i φ(n)}; real input, real-part output:
//   out = WHT( WHT(s) ⊙ cosφ ) / 2048     (all real arithmetic)
// One vector per 256-thread CTA (256 CTAs over 148 SMs). Amp bits:
//   0..2 regs, 3..7 lanes, 8..10 warps; one smem permute swaps regs<->warps.
// cosφ combined from 3 smem tables (built with fast __sincosf) -> no libm
// call in the per-thread critical path. Only 2 barriers total.
#define FDIM   2048
#define FNQ    11
#define FTHREADS 256
#define SPAD(n) ((n) + ((n) >> 5))

__global__ __launch_bounds__(FTHREADS, 2)
void rx_wht_kernel(const float* __restrict__ state,
                   const float* __restrict__ weights,
                   float* __restrict__ out,
                   int nvec, int nblocks)
{
    __shared__ float s_a[SPAD(FDIM - 1) + 1];
    __shared__ float TLc[32], TLs[32];   // lane-bit phases  (amp bits 3..7)
    __shared__ float TWc[8],  TWs[8];    // warp-bit phases  (amp bits 0..2)
    __shared__ float TJc[8],  TJs[8];    // reg-bit phases   (amp bits 8..10), /2048 folded

    const int tl  = threadIdx.x;
    const int w   = tl >> 5;             // 3 bits
    const int l   = tl & 31;             // 5 bits
    const int vec = blockIdx.x;
    const int bl  = vec % nblocks;
    const float* W = weights + bl * FNQ;

    float x[8];

    // Coalesced load of 8 consecutive real amplitudes
    {
        const float4* s4 = (const float4*)(state + (size_t)vec * FDIM) + tl * 2;
        const float4 v0 = s4[0];
        const float4 v1 = s4[1];
        x[0] = v0.x; x[1] = v0.y; x[2] = v0.z; x[3] = v0.w;
        x[4] = v1.x; x[5] = v1.y; x[6] = v1.z; x[7] = v1.w;
    }

    // Phase tables. Amp bit b hosts qubit (10-b); sign + if bit set else -.
    if (tl < 32) {
        // lane bits: amp bits 3..7 -> qubits 7..3
        float p = 0.0f;
        #pragma unroll
        for (int k = 0; k < 5; k++)
            p += ((tl >> k) & 1) ? 0.5f * W[7 - k] : -0.5f * W[7 - k];
        float s, c; __sincosf(p, &s, &c);
        TLc[tl] = c; TLs[tl] = s;
    } else if (tl < 64) {
        const int r = tl - 32;
        if (r < 8) {
            // warp bits: amp bits 0..2 -> qubits 10..8
            float p = 0.0f;
            #pragma unroll
            for (int b = 0; b < 3; b++)
                p += ((r >> b) & 1) ? 0.5f * W[10 - b] : -0.5f * W[10 - b];
            float s, c; __sincosf(p, &s, &c);
            TWc[r] = c; TWs[r] = s;
        } else if (r < 16) {
            // reg bits: amp bits 8..10 -> qubits 2..0, fold 1/2048
            const int j = r - 8;
            float p = 0.0f;
            #pragma unroll
            for (int t = 0; t < 3; t++)
                p += ((j >> t) & 1) ? 0.5f * W[2 - t] : -0.5f * W[2 - t];
            float s, c; __sincosf(p, &s, &c);
            TJc[j] = c * (1.0f / 2048.0f);
            TJs[j] = s * (1.0f / 2048.0f);
        }
    }

    // ---- forward WHT: reg bits 0..2 (amp bits 0..2 hosted in regs initially)
    #pragma unroll
    for (int b = 0; b < 3; b++) {
        const int m = 1 << b;
        #pragma unroll
        for (int j = 0; j < 8; j++)
            if ((j & m) == 0) {
                const int h = j | m;
                const float lo = x[j], hi = x[h];
                x[j] = lo + hi;
                x[h] = lo - hi;
            }
    }
    // ---- forward WHT: lane bits 3..7 (new = partner + sgn*own)
    #pragma unroll
    for (int k = 0; k < 5; k++) {
        const float sgn = ((l >> k) & 1) ? -1.0f : 1.0f;
        #pragma unroll
        for (int j = 0; j < 8; j++) {
            const float p = __shfl_xor_sync(0xffffffffu, x[j], 1 << k);
            x[j] = fmaf(sgn, x[j], p);
        }
    }
    // ---- permute: swap warp bits <-> reg bits (thread then holds
    //      amps m=(j<<8)|(l<<3)|w, i.e. amp bits 8..10 live in regs)
    #pragma unroll
    for (int j = 0; j < 8; j++)
        s_a[SPAD((tl << 3) | j)] = x[j];
    __syncthreads();                      // also publishes the phase tables
    #pragma unroll
    for (int j = 0; j < 8; j++)
        x[j] = s_a[SPAD((j << 8) | (l << 3) | w)];
    // ---- forward WHT: amp bits 8..10 (reg bits)
    #pragma unroll
    for (int b = 0; b < 3; b++) {
        const int m = 1 << b;
        #pragma unroll
        for (int j = 0; j < 8; j++)
            if ((j & m) == 0) {
                const int h = j | m;
                const float lo = x[j], hi = x[h];
                x[j] = lo + hi;
                x[h] = lo - hi;
            }
    }

    // ---- diagonal: x *= cos(φ_w + φ_l + φ_j)/2048, via angle addition
    {
        const float cw = TWc[w], sw = TWs[w];
        const float cl = TLc[l], sl = TLs[l];
        const float c1 = fmaf(cw, cl, -sw * sl);
        const float s1 = fmaf(sw, cl,  cw * sl);
        #pragma unroll
        for (int j = 0; j < 8; j++)
            x[j] *= fmaf(c1, TJc[j], -s1 * TJs[j]);
    }

    // ---- inverse WHT: amp bits 8..10
    #pragma unroll
    for (int b = 0; b < 3; b++) {
        const int m = 1 << b;
        #pragma unroll
        for (int j = 0; j < 8; j++)
            if ((j & m) == 0) {
                const int h = j | m;
                const float lo = x[j], hi = x[h];
                x[j] = lo + hi;
                x[h] = lo - hi;
            }
    }
    // ---- permute back (each thread rewrites exactly the slots it read:
    //      no barrier needed before these writes)
    #pragma unroll
    for (int j = 0; j < 8; j++)
        s_a[SPAD((j << 8) | (l << 3) | w)] = x[j];
    __syncthreads();
    #pragma unroll
    for (int j = 0; j < 8; j++)
        x[j] = s_a[SPAD((tl << 3) | j)];
    // ---- inverse WHT: lane bits 3..7
    #pragma unroll
    for (int k = 0; k < 5; k++) {
        const float sgn = ((l >> k) & 1) ? -1.0f : 1.0f;
        #pragma unroll
        for (int j = 0; j < 8; j++) {
            const float p = __shfl_xor_sync(0xffffffffu, x[j], 1 << k);
            x[j] = fmaf(sgn, x[j], p);
        }
    }
    // ---- inverse WHT: reg bits 0..2
    #pragma unroll
    for (int b = 0; b < 3; b++) {
        const int m = 1 << b;
        #pragma unroll
        for (int j = 0; j < 8; j++)
            if ((j & m) == 0) {
                const int h = j | m;
                const float lo = x[j], hi = x[h];
                x[j] = lo + hi;
                x[h] = lo - hi;
            }
    }

    // ---- coalesced real-only store
    float4* o4 = (float4*)out + (size_t)vec * (FDIM / 4) + tl * 2;
    o4[0] = make_float4(x[0], x[1], x[2], x[3]);
    o4[1] = make_float4(x[4], x[5], x[6], x[7]);
}

// ---------------- Generic fallback (proven R7 kernel, fully guarded).
__global__ __launch_bounds__(GTHREADS)
void rx_layer_kernel(const float* __restrict__ state,
                     const float* __restrict__ weights,
                     float* __restrict__ out,
                     int nvec, int nblocks, int nq, int dim,
                     long stateLimF, long wLimF, long outCapF,
                     int interleaved)
{
    __shared__ __align__(16) float2 amp[MAX_DIM];
    __shared__ float sa[32];
    __shared__ float sb[32];

    const int tid = threadIdx.x;

    for (int vec = blockIdx.x; vec < nvec; vec += gridDim.x) {
        const int bl = vec % nblocks;
        const long sbase = (long)vec * dim;
        for (int i = tid; i < dim; i += GTHREADS) {
            const long gi = sbase + i;
            amp[i] = make_float2((gi < stateLimF) ? state[gi] : 0.0f, 0.0f);
        }
        if (tid < nq) {
            const long widx = (long)bl * nq + tid;
            const float wv = (widx < wLimF) ? weights[widx] : 0.0f;
            float s, c;
            sincosf(wv * 0.5f, &s, &c);
            sa[tid] = c;
            sb[tid] = s;
        }
        __syncthreads();
        for (int q = 0; q < nq; q++) {
            const int   st   = 1 << (nq - 1 - q);
            const float a    = sa[q];
            const float b    = sb[q];
            const int   half = dim >> 1;
            for (int p = tid; p < half; p += GTHREADS) {
                const int lo = ((p & ~(st - 1)) << 1) | (p & (st - 1));
                const int hi = lo + st;
                const float2 xx = amp[lo];
                const float2 yy = amp[hi];
                amp[lo] = make_float2(fmaf(a, xx.x,  b * yy.y),
                                      fmaf(a, xx.y, -b * yy.x));
                amp[hi] = make_float2(fmaf(a, yy.x,  b * xx.y),
                                      fmaf(a, yy.y, -b * xx.x));
            }
            __syncthreads();
        }
        if (interleaved) {
            const long obase = 2L * (long)vec * dim;
            for (int i = tid; i < dim; i += GTHREADS) {
                const long fo = obase + 2L * i;
                if (fo + 1 < outCapF) {
                    out[fo]     = amp[i].x;
                    out[fo + 1] = amp[i].y;
                }
            }
        } else {
            const long obase = (long)vec * dim;
            for (int i = tid; i < dim; i += GTHREADS) {
                const long fo = obase + i;
                if (fo < outCapF) out[fo] = amp[i].x;
            }
        }
        __syncthreads();
    }
}

extern "C" void kernel_launch(void* const* d_in, const int* in_sizes, int n_in,
                              void* d_out, int out_size)
{
    int si = 0;
    for (int i = 1; i < n_in; i++) if (in_sizes[i] > in_sizes[si]) si = i;
    int wi = (si == 0) ? ((n_in > 1) ? 1 : 0) : 0;

    const float* state   = (const float*)d_in[si];
    const float* weights = (const float*)d_in[wi];
    const long stateE = in_sizes[si];
    const long wE     = in_sizes[wi];

    int nq = -1, dim = 0, nvec = 0, nblocks = 1;
    for (int q = 1; q <= 20; q++) {
        if (wE <= 0 || wE % q) continue;
        const long d = 1L << q;
        if (d > MAX_DIM || stateE % d) continue;
        const long nv = stateE / d;
        const long nb = wE / q;
        if (nb <= 0 || nv % nb) continue;
        nq = q; dim = (int)d; nvec = (int)nv; nblocks = (int)nb;
    }
    if (nq < 0) { nq = 1; dim = 2; nvec = (int)(stateE >= 2 ? stateE / 2 : 1); nblocks = 1; }

    const long outCapF = out_size;   // floats: minimal safe interpretation
    const int interleaved = (outCapF >= 2L * (long)nvec * dim) ? 1 : 0;

    const bool fast = (nq == FNQ) && (dim == FDIM) && nvec >= 1 &&
                      (stateE == (long)nvec * FDIM) &&
                      (wE == (long)nblocks * FNQ) &&
                      !interleaved &&
                      (outCapF >= (long)nvec * FDIM);

    if (fast) {
        rx_wht_kernel<<<nvec, FTHREADS>>>(state, weights, (float*)d_out,
                                          nvec, nblocks);
    } else {
        int grid = nvec < 2048 ? nvec : 2048;
        if (grid < 1) grid = 1;
        rx_layer_kernel<<<grid, GTHREADS>>>(state, weights, (float*)d_out,
                                            nvec, nblocks, nq, dim,
                                            stateE, wE, outCapF, interleaved);
    }
}

// round 11
// speedup vs baseline: 1.3544x; 1.0049x over previous
#include <cuda_runtime.h>
#include <math.h>

#define MAX_DIM 2048
#define GTHREADS 256

// ---------------- Fast path: nq=11, real-only output, ILP-2.
// U = (⊗H) D (⊗H), D(n)=e^{i φ(n)}; real input, real-part output:
//   out = WHT( WHT(s) ⊙ cosφ ) / 2048     (all real arithmetic)
// Each 256-thread CTA processes TWO vectors interleaved in registers
// (x[2][8]): doubles ILP on every latency edge and gives 128 CTAs =
// exactly one wave on 148 SMs (no tail). Amp bits: 0..2 regs, 3..7 lanes,
// 8..10 warps; one smem permute swaps regs<->warps. cosφ from smem tables
// (fast __sincosf), combined per-thread by angle addition. 2 barriers.
#define FDIM   2048
#define FNQ    11
#define FTHREADS 256
#define SPAD(n) ((n) + ((n) >> 5))

__global__ __launch_bounds__(FTHREADS, 2)
void rx_wht2_kernel(const float* __restrict__ state,
                    const float* __restrict__ weights,
                    float* __restrict__ out,
                    int nvec, int nblocks)
{
    __shared__ float s_a[2][SPAD(FDIM - 1) + 1];
    __shared__ float TLc[2][32], TLs[2][32];  // lane-bit phases (amp bits 3..7)
    __shared__ float TWc[2][8],  TWs[2][8];   // warp-bit phases (amp bits 0..2)
    __shared__ float TJc[2][8],  TJs[2][8];   // reg-bit phases  (amp bits 8..10), /2048 folded

    const int tl = threadIdx.x;
    const int w  = tl >> 5;              // 3 bits
    const int l  = tl & 31;              // 5 bits
    const int v0 = blockIdx.x * 2;

    float x[2][8];

    // Coalesced loads for both vectors, issued back-to-back (MLP=4)
    #pragma unroll
    for (int v = 0; v < 2; v++) {
        const int vec = v0 + v;
        if (vec < nvec) {
            const float4* s4 = (const float4*)(state + (size_t)vec * FDIM) + tl * 2;
            const float4 a = s4[0];
            const float4 b = s4[1];
            x[v][0] = a.x; x[v][1] = a.y; x[v][2] = a.z; x[v][3] = a.w;
            x[v][4] = b.x; x[v][5] = b.y; x[v][6] = b.z; x[v][7] = b.w;
        } else {
            #pragma unroll
            for (int j = 0; j < 8; j++) x[v][j] = 0.0f;
        }
    }

    // Phase tables (amp bit b hosts qubit 10-b; + if bit set else -).
    if (tl < 64) {
        const int v = tl >> 5;
        const int i = tl & 31;
        const int vec = (v0 + v < nvec) ? v0 + v : v0;
        const float* W = weights + (vec % nblocks) * FNQ;
        float p = 0.0f;
        #pragma unroll
        for (int k = 0; k < 5; k++)
            p += ((i >> k) & 1) ? 0.5f * W[7 - k] : -0.5f * W[7 - k];
        float s, c; __sincosf(p, &s, &c);
        TLc[v][i] = c; TLs[v][i] = s;
    } else if (tl < 96) {
        const int r = tl - 64;           // 0..31
        const int v = r >> 4;            // vector select
        const int q = r & 15;            // 0..15
        const int vec = (v0 + v < nvec) ? v0 + v : v0;
        const float* W = weights + (vec % nblocks) * FNQ;
        if (q < 8) {
            // warp bits: amp bits 0..2 -> qubits 10..8
            float p = 0.0f;
            #pragma unroll
            for (int b = 0; b < 3; b++)
                p += ((q >> b) & 1) ? 0.5f * W[10 - b] : -0.5f * W[10 - b];
            float s, c; __sincosf(p, &s, &c);
            TWc[v][q] = c; TWs[v][q] = s;
        } else {
            // reg bits: amp bits 8..10 -> qubits 2..0, fold 1/2048
            const int j = q - 8;
            float p = 0.0f;
            #pragma unroll
            for (int t = 0; t < 3; t++)
                p += ((j >> t) & 1) ? 0.5f * W[2 - t] : -0.5f * W[2 - t];
            float s, c; __sincosf(p, &s, &c);
            TJc[v][j] = c * (1.0f / 2048.0f);
            TJs[v][j] = s * (1.0f / 2048.0f);
        }
    }

    // ---- forward WHT: reg bits (amp bits 0..2)
    #pragma unroll
    for (int b = 0; b < 3; b++) {
        const int m = 1 << b;
        #pragma unroll
        for (int j = 0; j < 8; j++)
            if ((j & m) == 0) {
                const int h = j | m;
                #pragma unroll
                for (int v = 0; v < 2; v++) {
                    const float lo = x[v][j], hi = x[v][h];
                    x[v][j] = lo + hi;
                    x[v][h] = lo - hi;
                }
            }
    }
    // ---- forward WHT: lane bits 3..7 (new = partner + sgn*own)
    #pragma unroll
    for (int k = 0; k < 5; k++) {
        const float sgn = ((l >> k) & 1) ? -1.0f : 1.0f;
        #pragma unroll
        for (int j = 0; j < 8; j++) {
            #pragma unroll
            for (int v = 0; v < 2; v++) {
                const float p = __shfl_xor_sync(0xffffffffu, x[v][j], 1 << k);
                x[v][j] = fmaf(sgn, x[v][j], p);
            }
        }
    }
    // ---- permute: swap warp bits <-> reg bits
    #pragma unroll
    for (int j = 0; j < 8; j++) {
        s_a[0][SPAD((tl << 3) | j)] = x[0][j];
        s_a[1][SPAD((tl << 3) | j)] = x[1][j];
    }
    __syncthreads();                     // also publishes the phase tables
    #pragma unroll
    for (int j = 0; j < 8; j++) {
        x[0][j] = s_a[0][SPAD((j << 8) | (l << 3) | w)];
        x[1][j] = s_a[1][SPAD((j << 8) | (l << 3) | w)];
    }
    // ---- forward WHT: amp bits 8..10 (now reg bits)
    #pragma unroll
    for (int b = 0; b < 3; b++) {
        const int m = 1 << b;
        #pragma unroll
        for (int j = 0; j < 8; j++)
            if ((j & m) == 0) {
                const int h = j | m;
                #pragma unroll
                for (int v = 0; v < 2; v++) {
                    const float lo = x[v][j], hi = x[v][h];
                    x[v][j] = lo + hi;
                    x[v][h] = lo - hi;
                }
            }
    }

    // ---- diagonal: x *= cos(φ_w + φ_l + φ_j)/2048
    #pragma unroll
    for (int v = 0; v < 2; v++) {
        const float cw = TWc[v][w], sw = TWs[v][w];
        const float cl = TLc[v][l], sl = TLs[v][l];
        const float c1 = fmaf(cw, cl, -sw * sl);
        const float s1 = fmaf(sw, cl,  cw * sl);
        #pragma unroll
        for (int j = 0; j < 8; j++)
            x[v][j] *= fmaf(c1, TJc[v][j], -s1 * TJs[v][j]);
    }

    // ---- inverse WHT: amp bits 8..10
    #pragma unroll
    for (int b = 0; b < 3; b++) {
        const int m = 1 << b;
        #pragma unroll
        for (int j = 0; j < 8; j++)
            if ((j & m) == 0) {
                const int h = j | m;
                #pragma unroll
                for (int v = 0; v < 2; v++) {
                    const float lo = x[v][j], hi = x[v][h];
                    x[v][j] = lo + hi;
                    x[v][h] = lo - hi;
                }
            }
    }
    // ---- permute back (threads rewrite exactly the slots they read)
    #pragma unroll
    for (int j = 0; j < 8; j++) {
        s_a[0][SPAD((j << 8) | (l << 3) | w)] = x[0][j];
        s_a[1][SPAD((j << 8) | (l << 3) | w)] = x[1][j];
    }
    __syncthreads();
    #pragma unroll
    for (int j = 0; j < 8; j++) {
        x[0][j] = s_a[0][SPAD((tl << 3) | j)];
        x[1][j] = s_a[1][SPAD((tl << 3) | j)];
    }
    // ---- inverse WHT: lane bits 3..7
    #pragma unroll
    for (int k = 0; k < 5; k++) {
        const float sgn = ((l >> k) & 1) ? -1.0f : 1.0f;
        #pragma unroll
        for (int j = 0; j < 8; j++) {
            #pragma unroll
            for (int v = 0; v < 2; v++) {
                const float p = __shfl_xor_sync(0xffffffffu, x[v][j], 1 << k);
                x[v][j] = fmaf(sgn, x[v][j], p);
            }
        }
    }
    // ---- inverse WHT: reg bits 0..2
    #pragma unroll
    for (int b = 0; b < 3; b++) {
        const int m = 1 << b;
        #pragma unroll
        for (int j = 0; j < 8; j++)
            if ((j & m) == 0) {
                const int h = j | m;
                #pragma unroll
                for (int v = 0; v < 2; v++) {
                    const float lo = x[v][j], hi = x[v][h];
                    x[v][j] = lo + hi;
                    x[v][h] = lo - hi;
                }
            }
    }

    // ---- coalesced real-only stores
    #pragma unroll
    for (int v = 0; v < 2; v++) {
        const int vec = v0 + v;
        if (vec < nvec) {
            float4* o4 = (float4*)out + (size_t)vec * (FDIM / 4) + tl * 2;
            o4[0] = make_float4(x[v][0], x[v][1], x[v][2], x[v][3]);
            o4[1] = make_float4(x[v][4], x[v][5], x[v][6], x[v][7]);
        }
    }
}

// ---------------- Generic fallback (proven R7 kernel, fully guarded).
__global__ __launch_bounds__(GTHREADS)
void rx_layer_kernel(const float* __restrict__ state,
                     const float* __restrict__ weights,
                     float* __restrict__ out,
                     int nvec, int nblocks, int nq, int dim,
                     long stateLimF, long wLimF, long outCapF,
                     int interleaved)
{
    __shared__ __align__(16) float2 amp[MAX_DIM];
    __shared__ float sa[32];
    __shared__ float sb[32];

    const int tid = threadIdx.x;

    for (int vec = blockIdx.x; vec < nvec; vec += gridDim.x) {
        const int bl = vec % nblocks;
        const long sbase = (long)vec * dim;
        for (int i = tid; i < dim; i += GTHREADS) {
            const long gi = sbase + i;
            amp[i] = make_float2((gi < stateLimF) ? state[gi] : 0.0f, 0.0f);
        }
        if (tid < nq) {
            const long widx = (long)bl * nq + tid;
            const float wv = (widx < wLimF) ? weights[widx] : 0.0f;
            float s, c;
            sincosf(wv * 0.5f, &s, &c);
            sa[tid] = c;
            sb[tid] = s;
        }
        __syncthreads();
        for (int q = 0; q < nq; q++) {
            const int   st   = 1 << (nq - 1 - q);
            const float a    = sa[q];
            const float b    = sb[q];
            const int   half = dim >> 1;
            for (int p = tid; p < half; p += GTHREADS) {
                const int lo = ((p & ~(st - 1)) << 1) | (p & (st - 1));
                const int hi = lo + st;
                const float2 xx = amp[lo];
                const float2 yy = amp[hi];
                amp[lo] = make_float2(fmaf(a, xx.x,  b * yy.y),
                                      fmaf(a, xx.y, -b * yy.x));
                amp[hi] = make_float2(fmaf(a, yy.x,  b * xx.y),
                                      fmaf(a, yy.y, -b * xx.x));
            }
            __syncthreads();
        }
        if (interleaved) {
            const long obase = 2L * (long)vec * dim;
            for (int i = tid; i < dim; i += GTHREADS) {
                const long fo = obase + 2L * i;
                if (fo + 1 < outCapF) {
                    out[fo]     = amp[i].x;
                    out[fo + 1] = amp[i].y;
                }
            }
        } else {
            const long obase = (long)vec * dim;
            for (int i = tid; i < dim; i += GTHREADS) {
                const long fo = obase + i;
                if (fo < outCapF) out[fo] = amp[i].x;
            }
        }
        __syncthreads();
    }
}

extern "C" void kernel_launch(void* const* d_in, const int* in_sizes, int n_in,
                              void* d_out, int out_size)
{
    int si = 0;
    for (int i = 1; i < n_in; i++) if (in_sizes[i] > in_sizes[si]) si = i;
    int wi = (si == 0) ? ((n_in > 1) ? 1 : 0) : 0;

    const float* state   = (const float*)d_in[si];
    const float* weights = (const float*)d_in[wi];
    const long stateE = in_sizes[si];
    const long wE     = in_sizes[wi];

    int nq = -1, dim = 0, nvec = 0, nblocks = 1;
    for (int q = 1; q <= 20; q++) {
        if (wE <= 0 || wE % q) continue;
        const long d = 1L << q;
        if (d > MAX_DIM || stateE % d) continue;
        const long nv = stateE / d;
        const long nb = wE / q;
        if (nb <= 0 || nv % nb) continue;
        nq = q; dim = (int)d; nvec = (int)nv; nblocks = (int)nb;
    }
    if (nq < 0) { nq = 1; dim = 2; nvec = (int)(stateE >= 2 ? stateE / 2 : 1); nblocks = 1; }

    const long outCapF = out_size;   // floats: minimal safe interpretation
    const int interleaved = (outCapF >= 2L * (long)nvec * dim) ? 1 : 0;

    const bool fast = (nq == FNQ) && (dim == FDIM) && nvec >= 1 &&
                      (stateE == (long)nvec * FDIM) &&
                      (wE == (long)nblocks * FNQ) &&
                      !interleaved &&
                      (outCapF >= (long)nvec * FDIM);

    if (fast) {
        const int grid = (nvec + 1) / 2;
        rx_wht2_kernel<<<grid, FTHREADS>>>(state, weights, (float*)d_out,
                                           nvec, nblocks);
    } else {
        int grid = nvec < 2048 ? nvec : 2048;
        if (grid < 1) grid = 1;
        rx_layer_kernel<<<grid, GTHREADS>>>(state, weights, (float*)d_out,
                                            nvec, nblocks, nq, dim,
                                            stateE, wE, outCapF, interleaved);
    }
}